// round 15
// baseline (speedup 1.0000x reference)
#include <cuda_runtime.h>
#include <cuda_fp16.h>
#include <math.h>
#include <stdint.h>

constexpr int D = 768;
constexpr int S = 2048;
constexpr int BMAX = 8;

// ---- fp16 operand storage (no cudaMalloc allowed) ----
__device__ __align__(256) __half g_Xhi[BMAX * S * D];                 // A of step4
__device__ __align__(256) __half g_XThi[BMAX * D * S];                // A+B of step2
__device__ __align__(256) __half g_Qhi[D * D];                        // A of step1
__device__ __align__(256) __half g_Khi[D * D];                        // B of step1
__device__ __align__(256) __half g_Mhi[D * D];                        // B of step3
__device__ __align__(256) __half g_Ghi[BMAX * D * D];                 // A of step3
__device__ __align__(256) __half g_Hhi[BMAX * D * D];                 // B of step4

// ============================ helpers ============================
__device__ __forceinline__ uint32_t smem_u32(const void* p) {
    uint32_t a;
    asm("{ .reg .u64 t; cvta.to.shared.u64 t, %1; cvt.u32.u64 %0, t; }" : "=r"(a) : "l"(p));
    return a;
}
__device__ __forceinline__ void cp_async16(uint32_t dst, const void* src) {
    asm volatile("cp.async.cg.shared.global [%0], [%1], 16;" :: "r"(dst), "l"(src) : "memory");
}
#define CP_COMMIT() asm volatile("cp.async.commit_group;" ::: "memory")
template <int N>
__device__ __forceinline__ void cp_wait() {
    asm volatile("cp.async.wait_group %0;" :: "n"(N) : "memory");
}

__device__ __forceinline__ uint32_t pack_h(__half a, __half b) {
    return (uint32_t)__half_as_ushort(b) << 16 | (uint32_t)__half_as_ushort(a);
}

// m16n8k16 fp16 MMA, fp32 accum (baseline PTX -> HMMA on sm_103)
__device__ __forceinline__ void mma16816(float c[4], const uint32_t a[4],
                                         uint32_t b0, uint32_t b1) {
    asm volatile(
        "mma.sync.aligned.m16n8k16.row.col.f32.f16.f16.f32 "
        "{%0,%1,%2,%3}, {%4,%5,%6,%7}, {%8,%9}, {%0,%1,%2,%3};"
        : "+f"(c[0]), "+f"(c[1]), "+f"(c[2]), "+f"(c[3])
        : "r"(a[0]), "r"(a[1]), "r"(a[2]), "r"(a[3]), "r"(b0), "r"(b1));
}

// Tile pitch: 32 halves per row = 64B data, 80B pitch (stride-5 granules ->
// no ldmatrix bank conflicts since 5 is coprime with 8).
constexpr int PITCH = 80;
constexpr int TILE_A = 128 * PITCH;          // 10240
constexpr int TILE_B = 128 * PITCH;          // 10240
constexpr int STAGE = TILE_A + TILE_B;
constexpr int SMEM_SZ = 2 * STAGE;           // 40960 -> 2 CTAs/SM

__device__ __forceinline__ void ldmA(uint32_t base, int mrow, int kbyte, int lane, uint32_t r[4]) {
    const int q = lane >> 3;
    const uint32_t addr = base + (uint32_t)(mrow + (lane & 7) + ((q & 1) << 3)) * PITCH
                               + kbyte + ((q >> 1) << 4);
    asm volatile("ldmatrix.sync.aligned.m8n8.x4.shared.b16 {%0,%1,%2,%3}, [%4];"
                 : "=r"(r[0]), "=r"(r[1]), "=r"(r[2]), "=r"(r[3]) : "r"(addr));
}
__device__ __forceinline__ void ldmB(uint32_t base, int nrow, int kbyte, int lane, uint32_t r[4]) {
    const int q = lane >> 3;
    const uint32_t addr = base + (uint32_t)(nrow + (lane & 7) + ((q >> 1) << 3)) * PITCH
                               + kbyte + ((q & 1) << 4);
    asm volatile("ldmatrix.sync.aligned.m8n8.x4.shared.b16 {%0,%1,%2,%3}, [%4];"
                 : "=r"(r[0]), "=r"(r[1]), "=r"(r[2]), "=r"(r[3]) : "r"(addr));
}

// load one [128 x 32] half K-chunk into smem tile (16B granules)
__device__ __forceinline__ void load_tile_g(uint32_t sbase, const __half* src,
                                            int K, int kc, int tid) {
    const char* s0 = reinterpret_cast<const char*>(src) + (size_t)kc * 64;
    const size_t rs = (size_t)K * 2;
    #pragma unroll
    for (int i = tid; i < 512; i += 256) {
        const int row = i >> 2, g = i & 3;
        cp_async16(sbase + row * PITCH + g * 16, s0 + (size_t)row * rs + g * 16);
    }
}

// ======================= split / transpose kernels =======================
__global__ __launch_bounds__(256) void split_kernel(
    const float* __restrict__ x, __half* __restrict__ hi, int n4)
{
    int i = blockIdx.x * blockDim.x + threadIdx.x;
    if (i >= n4) return;
    float4 v = reinterpret_cast<const float4*>(x)[i];
    uint32_t ph[2];
    ph[0] = pack_h(__float2half(v.x), __float2half(v.y));
    ph[1] = pack_h(__float2half(v.z), __float2half(v.w));
    reinterpret_cast<uint2*>(hi)[i] = make_uint2(ph[0], ph[1]);
}

// X [b0..][S][D] fp32 -> Xhi AND XThi, vectorized (float4 in, uint2 out).
// 32x32 tile per CTA, 256 threads: load phase 1 float4/thread, transpose
// phase 4 strided smem reads + 1 uint2/thread.
__global__ __launch_bounds__(256) void transplit_kernel(
    const float* __restrict__ X,
    __half* __restrict__ Xhi, __half* __restrict__ XThi)
{
    __shared__ float t[32][33];
    const int b = blockIdx.z;
    const int s0 = blockIdx.x * 32, d0 = blockIdx.y * 32;
    const int tid = threadIdx.x;
    // load mapping: 8 threads per row x 32 rows, each thread 1 float4
    const int ls = tid >> 3;            // s-row 0..31
    const int ld = (tid & 7) * 4;       // d-col 0,4,..28
    const float* Xb = X + (size_t)b * S * D;
    __half* xh = Xhi + (size_t)b * S * D;
    {
        const size_t o = (size_t)(s0 + ls) * D + d0 + ld;
        const float4 v = *reinterpret_cast<const float4*>(Xb + o);
        t[ls][ld + 0] = v.x; t[ls][ld + 1] = v.y;
        t[ls][ld + 2] = v.z; t[ls][ld + 3] = v.w;
        uint2 ph;
        ph.x = pack_h(__float2half(v.x), __float2half(v.y));
        ph.y = pack_h(__float2half(v.z), __float2half(v.w));
        *reinterpret_cast<uint2*>(xh + o) = ph;
    }
    __syncthreads();
    // transpose mapping: thread writes XT[d0+td][s0+ts..ts+3] (uint2)
    const int td = tid >> 3;            // d-row 0..31
    const int ts = (tid & 7) * 4;       // s-col 0,4,..28
    __half* hb = XThi + (size_t)b * D * S;
    {
        const float v0 = t[ts + 0][td];
        const float v1 = t[ts + 1][td];
        const float v2 = t[ts + 2][td];
        const float v3 = t[ts + 3][td];
        uint2 ph;
        ph.x = pack_h(__float2half(v0), __float2half(v1));
        ph.y = pack_h(__float2half(v2), __float2half(v3));
        const size_t o = (size_t)(d0 + td) * S + s0 + ts;
        *reinterpret_cast<uint2*>(hb + o) = ph;
    }
}

// ======================= fp16 1-pass MMA GEMM =======================
// C[m][n] = alpha * sum_k A[m][k]*B[n][k]; A [MxK] rows, B [NxK] rows, K-major.
// CTA tile 128x128, BK=32, 8 warps of 64x32, 2 CTAs/SM.
// EPI=0: fp32 out. EPI=2: fp16 out. MIRROR: symmetric C mirror-write.
template <int EPI, bool MIRROR>
__global__ __launch_bounds__(256, 2) void mma_gemm(
    const __half* __restrict__ Ahi_, const __half* __restrict__ Bhi_,
    float* __restrict__ outF, __half* __restrict__ outHi,
    int K, int ldC, long long sA, long long sB, long long sC, float alpha)
{
    if (MIRROR && blockIdx.x > blockIdx.y) return;

    extern __shared__ __align__(128) char smem[];
    const uint32_t sb = smem_u32(smem);
    const int tid = threadIdx.x;
    const int lane = tid & 31, wid = tid >> 5;
    const int wm = wid & 1;        // 2 m-slots of 64
    const int wn = wid >> 1;       // 4 n-slots of 32

    const size_t zb = blockIdx.z;
    const int m0 = blockIdx.y * 128, n0 = blockIdx.x * 128;
    const __half* Ahi = Ahi_ + zb * sA + (size_t)m0 * K;
    const __half* Bhi = Bhi_ + zb * sB + (size_t)n0 * K;

    float acc[4][4][4] = {};   // [mt][nt][frag]

    auto issue = [&](int stage, int kc) {
        const uint32_t s = sb + stage * STAGE;
        load_tile_g(s,          Ahi, K, kc, tid);
        load_tile_g(s + TILE_A, Bhi, K, kc, tid);
        CP_COMMIT();
    };

    const int KC = K >> 5;
    issue(0, 0);

    for (int kc = 0; kc < KC; kc++) {
        const int st = kc & 1;
        const bool more = (kc + 1) < KC;
        if (more) issue(st ^ 1, kc + 1);
        if (more) cp_wait<1>(); else cp_wait<0>();
        __syncthreads();

        const uint32_t sAhi = sb + st * STAGE;
        const uint32_t sBhi = sAhi + TILE_A;
        const int nrow = wn * 32;
        const int mrow = wm * 64;

        #pragma unroll
        for (int ks = 0; ks < 2; ks++) {
            const int kbyte = ks * 32;
            uint32_t bh[2][4];
            ldmB(sBhi, nrow,      kbyte, lane, bh[0]);
            ldmB(sBhi, nrow + 16, kbyte, lane, bh[1]);
            #pragma unroll
            for (int mt = 0; mt < 4; mt++) {
                uint32_t ah[4];
                ldmA(sAhi, mrow + mt * 16, kbyte, lane, ah);
                #pragma unroll
                for (int nt = 0; nt < 4; nt++) {
                    const uint32_t b0 = bh[nt >> 1][(nt & 1) * 2];
                    const uint32_t b1 = bh[nt >> 1][(nt & 1) * 2 + 1];
                    mma16816(acc[mt][nt], ah, b0, b1);
                }
            }
        }
        __syncthreads();
    }

    // ---- epilogue ----
    const int r0 = lane >> 2;
    const int c0 = (lane & 3) * 2;
    const bool mir = MIRROR && (blockIdx.x != blockIdx.y);
    #pragma unroll
    for (int mt = 0; mt < 4; mt++) {
        #pragma unroll
        for (int half = 0; half < 2; half++) {
            const size_t m = (size_t)(m0 + wm * 64 + mt * 16 + r0 + half * 8);
            #pragma unroll
            for (int nt = 0; nt < 4; nt++) {
                const size_t n = (size_t)(n0 + wn * 32 + nt * 8 + c0);
                const float v0 = acc[mt][nt][half * 2 + 0] * alpha;
                const float v1 = acc[mt][nt][half * 2 + 1] * alpha;
                if (EPI == 0) {
                    float2 v = make_float2(v0, v1);
                    *reinterpret_cast<float2*>(outF + zb * sC + m * ldC + n) = v;
                } else {  // EPI == 2: fp16 out (+ mirror)
                    __half h0 = __float2half(v0);
                    __half h1 = __float2half(v1);
                    const size_t o = zb * sC + m * ldC + n;
                    *reinterpret_cast<uint32_t*>(outHi + o) = pack_h(h0, h1);
                    if (mir) {
                        const size_t ot = zb * sC + n * ldC + m;
                        outHi[ot] = h0;
                        outHi[ot + ldC] = h1;
                    }
                }
            }
        }
    }
}

// ============================== launcher ==============================
extern "C" void kernel_launch(void* const* d_in, const int* in_sizes, int n_in,
                              void* d_out, int out_size)
{
    const float* X  = (const float*)d_in[0];
    const float* Wq = (const float*)d_in[2];
    const float* Wk = (const float*)d_in[3];
    float* out = (float*)d_out;
    const int B = in_sizes[1];  // 8

    struct Ptrs {
        __half *Xhi, *XThi, *Qhi, *Khi, *Mhi, *Ghi, *Hhi;
    };
    static Ptrs p;
    static cudaStream_t sW = nullptr;
    static cudaEvent_t evA = nullptr, evB = nullptr;  // reused (re-recorded)
    static bool inited = false;
    if (!inited) {
        cudaGetSymbolAddress((void**)&p.Xhi, g_Xhi);
        cudaGetSymbolAddress((void**)&p.XThi, g_XThi);
        cudaGetSymbolAddress((void**)&p.Qhi, g_Qhi);
        cudaGetSymbolAddress((void**)&p.Khi, g_Khi);
        cudaGetSymbolAddress((void**)&p.Mhi, g_Mhi);
        cudaGetSymbolAddress((void**)&p.Ghi, g_Ghi);
        cudaGetSymbolAddress((void**)&p.Hhi, g_Hhi);
        cudaFuncSetAttribute((const void*)mma_gemm<2, false>,
                             cudaFuncAttributeMaxDynamicSharedMemorySize, SMEM_SZ);
        cudaFuncSetAttribute((const void*)mma_gemm<2, true>,
                             cudaFuncAttributeMaxDynamicSharedMemorySize, SMEM_SZ);
        cudaFuncSetAttribute((const void*)mma_gemm<0, false>,
                             cudaFuncAttributeMaxDynamicSharedMemorySize, SMEM_SZ);
        cudaStreamCreateWithFlags(&sW, cudaStreamNonBlocking);
        cudaEventCreateWithFlags(&evA, cudaEventDisableTiming);
        cudaEventCreateWithFlags(&evB, cudaEventDisableTiming);
        inited = true;
    }

    const float alpha = 1.0f / sqrtf((float)D * (float)D * (float)D);
    const long long DD = (long long)D * D;
    const long long SD = (long long)S * D;
    const int h = B / 2;         // batches [0,h) on main, [h,B) on sW
    const int h2 = B - h;

    // Event protocol (re-recorded events; each wait binds to the most recent
    // prior record in host issue order — capture-legal):
    //   evA rec#1: input ready (main)  -> sW starts W path + its half
    //   evB rec#1: M ready (sW)        -> main waits before its step3
    //   evB rec#2: sW half done        -> main waits at the end

    // (1) fork
    cudaEventRecord(evA, 0);
    cudaStreamWaitEvent(sW, evA, 0);

    // (2) sW: W path, then its half's transplit + GEMM chain
    {
        int n4 = D * D / 4;
        split_kernel<<<(n4 + 255) / 256, 256, 0, sW>>>(Wq, p.Qhi, n4);
        split_kernel<<<(n4 + 255) / 256, 256, 0, sW>>>(Wk, p.Khi, n4);
        mma_gemm<2, false><<<dim3(D / 128, D / 128, 1), 256, SMEM_SZ, sW>>>(
            p.Qhi, p.Khi, nullptr, p.Mhi, D, D, 0, 0, 0, 1.0f);
    }
    cudaEventRecord(evB, sW);            // rec#1: M ready
    transplit_kernel<<<dim3(S / 32, D / 32, h2), 256, 0, sW>>>(
        X + (size_t)h * SD, p.Xhi + (size_t)h * SD, p.XThi + (size_t)h * SD);
    mma_gemm<2, true><<<dim3(D / 128, D / 128, h2), 256, SMEM_SZ, sW>>>(
        p.XThi + (size_t)h * SD, p.XThi + (size_t)h * SD, nullptr,
        p.Ghi + (size_t)h * DD, S, D, SD, SD, DD, 1.0f);
    mma_gemm<2, false><<<dim3(D / 128, D / 128, h2), 256, SMEM_SZ, sW>>>(
        p.Ghi + (size_t)h * DD, p.Mhi, nullptr,
        p.Hhi + (size_t)h * DD, D, D, DD, 0, DD, alpha);
    mma_gemm<0, false><<<dim3(D / 128, S / 128, h2), 256, SMEM_SZ, sW>>>(
        p.Xhi + (size_t)h * SD, p.Hhi + (size_t)h * DD,
        out + (size_t)h * SD, nullptr, D, D, SD, DD, SD, 1.0f);
    cudaEventRecord(evB, sW);            // rec#2: sW half done
    // NOTE: main's wait below binds rec#1 only because it is issued BEFORE
    // rec#2 in host order — see ordering of calls (step3 wait issued next).

    // (3) main: its half's transplit + GEMM chain
    transplit_kernel<<<dim3(S / 32, D / 32, h), 256>>>(X, p.Xhi, p.XThi);
    mma_gemm<2, true><<<dim3(D / 128, D / 128, h), 256, SMEM_SZ>>>(
        p.XThi, p.XThi, nullptr, p.Ghi, S, D, SD, SD, DD, 1.0f);
    cudaStreamWaitEvent(0, evB, 0);      // binds to latest record = rec#2
    mma_gemm<2, false><<<dim3(D / 128, D / 128, h), 256, SMEM_SZ>>>(
        p.Ghi, p.Mhi, nullptr, p.Hhi, D, D, DD, 0, DD, alpha);
    mma_gemm<0, false><<<dim3(D / 128, S / 128, h), 256, SMEM_SZ>>>(
        p.Xhi, p.Hhi, out, nullptr, D, D, SD, DD, SD, 1.0f);
    // rec#2 wait above already covers rec#1 (M ready precedes sW-half-done
    // in sW program order), so M is valid before main's step3, and the sW
    // half is complete before main's final kernels finish -> stream 0 end
    // state is the full output.
}

// round 16
// speedup vs baseline: 1.1668x; 1.1668x over previous
#include <cuda_runtime.h>
#include <cuda_fp16.h>
#include <math.h>
#include <stdint.h>

constexpr int D = 768;
constexpr int S = 2048;
constexpr int BMAX = 8;

// ---- fp16 operand storage (no cudaMalloc allowed) ----
__device__ __align__(256) __half g_Xhi[BMAX * S * D];                 // A of step4
__device__ __align__(256) __half g_XThi[BMAX * D * S];                // A+B of step2
__device__ __align__(256) __half g_Qhi[D * D];                        // A of step1
__device__ __align__(256) __half g_Khi[D * D];                        // B of step1
__device__ __align__(256) __half g_Mhi[D * D];                        // B of step3
__device__ __align__(256) __half g_Ghi[BMAX * D * D];                 // A of step3
__device__ __align__(256) __half g_Hhi[BMAX * D * D];                 // B of step4

// ============================ helpers ============================
__device__ __forceinline__ uint32_t smem_u32(const void* p) {
    uint32_t a;
    asm("{ .reg .u64 t; cvta.to.shared.u64 t, %1; cvt.u32.u64 %0, t; }" : "=r"(a) : "l"(p));
    return a;
}
__device__ __forceinline__ void cp_async16(uint32_t dst, const void* src) {
    asm volatile("cp.async.cg.shared.global [%0], [%1], 16;" :: "r"(dst), "l"(src) : "memory");
}
#define CP_COMMIT() asm volatile("cp.async.commit_group;" ::: "memory")
template <int N>
__device__ __forceinline__ void cp_wait() {
    asm volatile("cp.async.wait_group %0;" :: "n"(N) : "memory");
}

__device__ __forceinline__ uint32_t pack_h(__half a, __half b) {
    return (uint32_t)__half_as_ushort(b) << 16 | (uint32_t)__half_as_ushort(a);
}

// m16n8k16 fp16 MMA, fp32 accum (baseline PTX -> HMMA on sm_103)
__device__ __forceinline__ void mma16816(float c[4], const uint32_t a[4],
                                         uint32_t b0, uint32_t b1) {
    asm volatile(
        "mma.sync.aligned.m16n8k16.row.col.f32.f16.f16.f32 "
        "{%0,%1,%2,%3}, {%4,%5,%6,%7}, {%8,%9}, {%0,%1,%2,%3};"
        : "+f"(c[0]), "+f"(c[1]), "+f"(c[2]), "+f"(c[3])
        : "r"(a[0]), "r"(a[1]), "r"(a[2]), "r"(a[3]), "r"(b0), "r"(b1));
}

// Tile pitch: 32 halves per row = 64B data, 80B pitch (stride-5 granules ->
// no ldmatrix bank conflicts since 5 is coprime with 8).
constexpr int PITCH = 80;
constexpr int TILE_A = 128 * PITCH;          // 10240
constexpr int TILE_B = 128 * PITCH;          // 10240
constexpr int STAGE = TILE_A + TILE_B;
constexpr int SMEM_SZ = 2 * STAGE;           // 40960 -> 2 CTAs/SM

__device__ __forceinline__ void ldmA(uint32_t base, int mrow, int kbyte, int lane, uint32_t r[4]) {
    const int q = lane >> 3;
    const uint32_t addr = base + (uint32_t)(mrow + (lane & 7) + ((q & 1) << 3)) * PITCH
                               + kbyte + ((q >> 1) << 4);
    asm volatile("ldmatrix.sync.aligned.m8n8.x4.shared.b16 {%0,%1,%2,%3}, [%4];"
                 : "=r"(r[0]), "=r"(r[1]), "=r"(r[2]), "=r"(r[3]) : "r"(addr));
}
__device__ __forceinline__ void ldmB(uint32_t base, int nrow, int kbyte, int lane, uint32_t r[4]) {
    const int q = lane >> 3;
    const uint32_t addr = base + (uint32_t)(nrow + (lane & 7) + ((q >> 1) << 3)) * PITCH
                               + kbyte + ((q & 1) << 4);
    asm volatile("ldmatrix.sync.aligned.m8n8.x4.shared.b16 {%0,%1,%2,%3}, [%4];"
                 : "=r"(r[0]), "=r"(r[1]), "=r"(r[2]), "=r"(r[3]) : "r"(addr));
}

// load one [128 x 32] half K-chunk into smem tile (16B granules)
__device__ __forceinline__ void load_tile_g(uint32_t sbase, const __half* src,
                                            int K, int kc, int tid) {
    const char* s0 = reinterpret_cast<const char*>(src) + (size_t)kc * 64;
    const size_t rs = (size_t)K * 2;
    #pragma unroll
    for (int i = tid; i < 512; i += 256) {
        const int row = i >> 2, g = i & 3;
        cp_async16(sbase + row * PITCH + g * 16, s0 + (size_t)row * rs + g * 16);
    }
}

// ======================= split / transpose kernels =======================
__global__ __launch_bounds__(256) void split_kernel(
    const float* __restrict__ x, __half* __restrict__ hi, int n4)
{
    int i = blockIdx.x * blockDim.x + threadIdx.x;
    if (i >= n4) return;
    float4 v = reinterpret_cast<const float4*>(x)[i];
    uint32_t ph[2];
    ph[0] = pack_h(__float2half(v.x), __float2half(v.y));
    ph[1] = pack_h(__float2half(v.z), __float2half(v.w));
    reinterpret_cast<uint2*>(hi)[i] = make_uint2(ph[0], ph[1]);
}

// X [B][S][D] fp32 -> Xhi AND XThi, vectorized (float4 in, uint2 out).
// 32x32 tile per CTA, 256 threads: load phase 1 float4/thread, transpose
// phase 4 strided smem reads + 1 uint2/thread.
__global__ __launch_bounds__(256) void transplit_kernel(
    const float* __restrict__ X,
    __half* __restrict__ Xhi, __half* __restrict__ XThi)
{
    __shared__ float t[32][33];
    const int b = blockIdx.z;
    const int s0 = blockIdx.x * 32, d0 = blockIdx.y * 32;
    const int tid = threadIdx.x;
    // load mapping: 8 threads per row x 32 rows, each thread 1 float4
    const int ls = tid >> 3;            // s-row 0..31
    const int ld = (tid & 7) * 4;       // d-col 0,4,..28
    const float* Xb = X + (size_t)b * S * D;
    __half* xh = Xhi + (size_t)b * S * D;
    {
        const size_t o = (size_t)(s0 + ls) * D + d0 + ld;
        const float4 v = *reinterpret_cast<const float4*>(Xb + o);
        t[ls][ld + 0] = v.x; t[ls][ld + 1] = v.y;
        t[ls][ld + 2] = v.z; t[ls][ld + 3] = v.w;
        uint2 ph;
        ph.x = pack_h(__float2half(v.x), __float2half(v.y));
        ph.y = pack_h(__float2half(v.z), __float2half(v.w));
        *reinterpret_cast<uint2*>(xh + o) = ph;
    }
    __syncthreads();
    // transpose mapping: thread writes XT[d0+td][s0+ts..ts+3] (uint2)
    const int td = tid >> 3;            // d-row 0..31
    const int ts = (tid & 7) * 4;       // s-col 0,4,..28
    __half* hb = XThi + (size_t)b * D * S;
    {
        const float v0 = t[ts + 0][td];
        const float v1 = t[ts + 1][td];
        const float v2 = t[ts + 2][td];
        const float v3 = t[ts + 3][td];
        uint2 ph;
        ph.x = pack_h(__float2half(v0), __float2half(v1));
        ph.y = pack_h(__float2half(v2), __float2half(v3));
        const size_t o = (size_t)(d0 + td) * S + s0 + ts;
        *reinterpret_cast<uint2*>(hb + o) = ph;
    }
}

// ======================= fp16 1-pass MMA GEMM =======================
// C[m][n] = alpha * sum_k A[m][k]*B[n][k]; A [MxK] rows, B [NxK] rows, K-major.
// CTA tile 128x128, BK=32, 8 warps of 64x32, 2 CTAs/SM.
// EPI=0: fp32 out. EPI=2: fp16 out. MIRROR: symmetric C mirror-write.
template <int EPI, bool MIRROR>
__global__ __launch_bounds__(256, 2) void mma_gemm(
    const __half* __restrict__ Ahi_, const __half* __restrict__ Bhi_,
    float* __restrict__ outF, __half* __restrict__ outHi,
    int K, int ldC, long long sA, long long sB, long long sC, float alpha)
{
    if (MIRROR && blockIdx.x > blockIdx.y) return;

    extern __shared__ __align__(128) char smem[];
    const uint32_t sb = smem_u32(smem);
    const int tid = threadIdx.x;
    const int lane = tid & 31, wid = tid >> 5;
    const int wm = wid & 1;        // 2 m-slots of 64
    const int wn = wid >> 1;       // 4 n-slots of 32

    const size_t zb = blockIdx.z;
    const int m0 = blockIdx.y * 128, n0 = blockIdx.x * 128;
    const __half* Ahi = Ahi_ + zb * sA + (size_t)m0 * K;
    const __half* Bhi = Bhi_ + zb * sB + (size_t)n0 * K;

    float acc[4][4][4] = {};   // [mt][nt][frag]

    auto issue = [&](int stage, int kc) {
        const uint32_t s = sb + stage * STAGE;
        load_tile_g(s,          Ahi, K, kc, tid);
        load_tile_g(s + TILE_A, Bhi, K, kc, tid);
        CP_COMMIT();
    };

    const int KC = K >> 5;
    issue(0, 0);

    for (int kc = 0; kc < KC; kc++) {
        const int st = kc & 1;
        const bool more = (kc + 1) < KC;
        if (more) issue(st ^ 1, kc + 1);
        if (more) cp_wait<1>(); else cp_wait<0>();
        __syncthreads();

        const uint32_t sAhi = sb + st * STAGE;
        const uint32_t sBhi = sAhi + TILE_A;
        const int nrow = wn * 32;
        const int mrow = wm * 64;

        #pragma unroll
        for (int ks = 0; ks < 2; ks++) {
            const int kbyte = ks * 32;
            uint32_t bh[2][4];
            ldmB(sBhi, nrow,      kbyte, lane, bh[0]);
            ldmB(sBhi, nrow + 16, kbyte, lane, bh[1]);
            #pragma unroll
            for (int mt = 0; mt < 4; mt++) {
                uint32_t ah[4];
                ldmA(sAhi, mrow + mt * 16, kbyte, lane, ah);
                #pragma unroll
                for (int nt = 0; nt < 4; nt++) {
                    const uint32_t b0 = bh[nt >> 1][(nt & 1) * 2];
                    const uint32_t b1 = bh[nt >> 1][(nt & 1) * 2 + 1];
                    mma16816(acc[mt][nt], ah, b0, b1);
                }
            }
        }
        __syncthreads();
    }

    // ---- epilogue ----
    const int r0 = lane >> 2;
    const int c0 = (lane & 3) * 2;
    const bool mir = MIRROR && (blockIdx.x != blockIdx.y);
    #pragma unroll
    for (int mt = 0; mt < 4; mt++) {
        #pragma unroll
        for (int half = 0; half < 2; half++) {
            const size_t m = (size_t)(m0 + wm * 64 + mt * 16 + r0 + half * 8);
            #pragma unroll
            for (int nt = 0; nt < 4; nt++) {
                const size_t n = (size_t)(n0 + wn * 32 + nt * 8 + c0);
                const float v0 = acc[mt][nt][half * 2 + 0] * alpha;
                const float v1 = acc[mt][nt][half * 2 + 1] * alpha;
                if (EPI == 0) {
                    float2 v = make_float2(v0, v1);
                    *reinterpret_cast<float2*>(outF + zb * sC + m * ldC + n) = v;
                } else {  // EPI == 2: fp16 out (+ mirror)
                    __half h0 = __float2half(v0);
                    __half h1 = __float2half(v1);
                    const size_t o = zb * sC + m * ldC + n;
                    *reinterpret_cast<uint32_t*>(outHi + o) = pack_h(h0, h1);
                    if (mir) {
                        const size_t ot = zb * sC + n * ldC + m;
                        outHi[ot] = h0;
                        outHi[ot + ldC] = h1;
                    }
                }
            }
        }
    }
}

// ============================== launcher ==============================
// R13 structure (best known): single main chain with batched grids; W path
// forked on one side stream with a dedicated join event before step 3.
extern "C" void kernel_launch(void* const* d_in, const int* in_sizes, int n_in,
                              void* d_out, int out_size)
{
    const float* X  = (const float*)d_in[0];
    const float* Wq = (const float*)d_in[2];
    const float* Wk = (const float*)d_in[3];
    float* out = (float*)d_out;
    const int B = in_sizes[1];  // 8

    struct Ptrs {
        __half *Xhi, *XThi, *Qhi, *Khi, *Mhi, *Ghi, *Hhi;
    };
    static Ptrs p;
    static cudaStream_t sW = nullptr;
    static cudaEvent_t evFork = nullptr, evJoin = nullptr;
    static bool inited = false;
    if (!inited) {
        cudaGetSymbolAddress((void**)&p.Xhi, g_Xhi);
        cudaGetSymbolAddress((void**)&p.XThi, g_XThi);
        cudaGetSymbolAddress((void**)&p.Qhi, g_Qhi);
        cudaGetSymbolAddress((void**)&p.Khi, g_Khi);
        cudaGetSymbolAddress((void**)&p.Mhi, g_Mhi);
        cudaGetSymbolAddress((void**)&p.Ghi, g_Ghi);
        cudaGetSymbolAddress((void**)&p.Hhi, g_Hhi);
        cudaFuncSetAttribute((const void*)mma_gemm<2, false>,
                             cudaFuncAttributeMaxDynamicSharedMemorySize, SMEM_SZ);
        cudaFuncSetAttribute((const void*)mma_gemm<2, true>,
                             cudaFuncAttributeMaxDynamicSharedMemorySize, SMEM_SZ);
        cudaFuncSetAttribute((const void*)mma_gemm<0, false>,
                             cudaFuncAttributeMaxDynamicSharedMemorySize, SMEM_SZ);
        cudaStreamCreateWithFlags(&sW, cudaStreamNonBlocking);
        cudaEventCreateWithFlags(&evFork, cudaEventDisableTiming);
        cudaEventCreateWithFlags(&evJoin, cudaEventDisableTiming);
        inited = true;
    }

    const float alpha = 1.0f / sqrtf((float)D * (float)D * (float)D);
    const long long DD = (long long)D * D;
    const long long SD = (long long)S * D;

    // ---- fork: W path (splits + step1) on side stream ----
    cudaEventRecord(evFork, 0);
    cudaStreamWaitEvent(sW, evFork, 0);
    {
        int n4 = D * D / 4;
        split_kernel<<<(n4 + 255) / 256, 256, 0, sW>>>(Wq, p.Qhi, n4);
        split_kernel<<<(n4 + 255) / 256, 256, 0, sW>>>(Wk, p.Khi, n4);
        // 1) M = Wq @ Wk^T   [768x768], K=768 -> fp16
        mma_gemm<2, false><<<dim3(D / 128, D / 128, 1), 256, SMEM_SZ, sW>>>(
            p.Qhi, p.Khi, nullptr, p.Mhi, D, D, 0, 0, 0, 1.0f);
    }
    cudaEventRecord(evJoin, sW);

    // ---- main chain ----
    {
        dim3 g(S / 32, D / 32, B);
        transplit_kernel<<<g, 256>>>(X, p.Xhi, p.XThi);
    }
    // 2) G_b = XThi_b @ XThi_b^T  [768x768] x B, K=2048 (symmetric, mirrored)
    mma_gemm<2, true><<<dim3(D / 128, D / 128, B), 256, SMEM_SZ>>>(
        p.XThi, p.XThi, nullptr, p.Ghi, S, D, SD, SD, DD, 1.0f);

    cudaStreamWaitEvent(0, evJoin, 0);  // join W path before step3

    // 3) H^T_b = (G_b @ M^T) * alpha  [768x768] x B, K=768 -> fp16
    mma_gemm<2, false><<<dim3(D / 128, D / 128, B), 256, SMEM_SZ>>>(
        p.Ghi, p.Mhi, nullptr, p.Hhi, D, D, DD, 0, DD, alpha);
    // 4) Out_b = Xhi_b @ (H^T_b)^T  [2048x768] x B, K=768 -> fp32
    mma_gemm<0, false><<<dim3(D / 128, S / 128, B), 256, SMEM_SZ>>>(
        p.Xhi, p.Hhi, out, nullptr, D, D, SD, DD, SD, 1.0f);
}

// round 17
// speedup vs baseline: 1.2476x; 1.0692x over previous
#include <cuda_runtime.h>
#include <cuda_fp16.h>
#include <math.h>
#include <stdint.h>

constexpr int D = 768;
constexpr int S = 2048;
constexpr int BMAX = 8;

// ---- fp16 operand storage (no cudaMalloc allowed) ----
__device__ __align__(256) __half g_Xhi[BMAX * S * D];                 // A of step4
__device__ __align__(256) __half g_XThi[BMAX * D * S];                // A+B of step2
__device__ __align__(256) __half g_Qhi[D * D];                        // A of step1
__device__ __align__(256) __half g_Khi[D * D];                        // B of step1
__device__ __align__(256) __half g_Mhi[D * D];                        // B of step3
__device__ __align__(256) __half g_Ghi[BMAX * D * D];                 // A of step3
__device__ __align__(256) __half g_Hhi[BMAX * D * D];                 // B of step4

// ============================ helpers ============================
__device__ __forceinline__ uint32_t smem_u32(const void* p) {
    uint32_t a;
    asm("{ .reg .u64 t; cvta.to.shared.u64 t, %1; cvt.u32.u64 %0, t; }" : "=r"(a) : "l"(p));
    return a;
}
__device__ __forceinline__ void cp_async16(uint32_t dst, const void* src) {
    asm volatile("cp.async.cg.shared.global [%0], [%1], 16;" :: "r"(dst), "l"(src) : "memory");
}
#define CP_COMMIT() asm volatile("cp.async.commit_group;" ::: "memory")
template <int N>
__device__ __forceinline__ void cp_wait() {
    asm volatile("cp.async.wait_group %0;" :: "n"(N) : "memory");
}

__device__ __forceinline__ uint32_t pack_h(__half a, __half b) {
    return (uint32_t)__half_as_ushort(b) << 16 | (uint32_t)__half_as_ushort(a);
}

// m16n8k16 fp16 MMA, fp32 accum (baseline PTX -> HMMA on sm_103)
__device__ __forceinline__ void mma16816(float c[4], const uint32_t a[4],
                                         uint32_t b0, uint32_t b1) {
    asm volatile(
        "mma.sync.aligned.m16n8k16.row.col.f32.f16.f16.f32 "
        "{%0,%1,%2,%3}, {%4,%5,%6,%7}, {%8,%9}, {%0,%1,%2,%3};"
        : "+f"(c[0]), "+f"(c[1]), "+f"(c[2]), "+f"(c[3])
        : "r"(a[0]), "r"(a[1]), "r"(a[2]), "r"(a[3]), "r"(b0), "r"(b1));
}

// Tile pitch: 32 halves per row = 64B data, 80B pitch (stride-5 granules ->
// no ldmatrix bank conflicts since 5 is coprime with 8).
constexpr int PITCH = 80;
constexpr int TILE_A = 128 * PITCH;          // 10240
constexpr int TILE_B = 128 * PITCH;          // 10240
constexpr int STAGE = TILE_A + TILE_B;
constexpr int SMEM_SZ = 2 * STAGE;           // 40960 -> 2 CTAs/SM

// 64x64 variant (step2)
constexpr int TILE64 = 64 * PITCH;           // 5120
constexpr int STAGE64 = 2 * TILE64;          // 10240
constexpr int SMEM64 = 2 * STAGE64;          // 20480 -> many CTAs/SM

__device__ __forceinline__ void ldmA(uint32_t base, int mrow, int kbyte, int lane, uint32_t r[4]) {
    const int q = lane >> 3;
    const uint32_t addr = base + (uint32_t)(mrow + (lane & 7) + ((q & 1) << 3)) * PITCH
                               + kbyte + ((q >> 1) << 4);
    asm volatile("ldmatrix.sync.aligned.m8n8.x4.shared.b16 {%0,%1,%2,%3}, [%4];"
                 : "=r"(r[0]), "=r"(r[1]), "=r"(r[2]), "=r"(r[3]) : "r"(addr));
}
__device__ __forceinline__ void ldmB(uint32_t base, int nrow, int kbyte, int lane, uint32_t r[4]) {
    const int q = lane >> 3;
    const uint32_t addr = base + (uint32_t)(nrow + (lane & 7) + ((q >> 1) << 3)) * PITCH
                               + kbyte + ((q & 1) << 4);
    asm volatile("ldmatrix.sync.aligned.m8n8.x4.shared.b16 {%0,%1,%2,%3}, [%4];"
                 : "=r"(r[0]), "=r"(r[1]), "=r"(r[2]), "=r"(r[3]) : "r"(addr));
}

// load one [rows x 32] half K-chunk into smem tile (16B granules)
template <int ROWS, int THREADS>
__device__ __forceinline__ void load_tile_t(uint32_t sbase, const __half* src,
                                            int K, int kc, int tid) {
    const char* s0 = reinterpret_cast<const char*>(src) + (size_t)kc * 64;
    const size_t rs = (size_t)K * 2;
    #pragma unroll
    for (int i = tid; i < ROWS * 4; i += THREADS) {
        const int row = i >> 2, g = i & 3;
        cp_async16(sbase + row * PITCH + g * 16, s0 + (size_t)row * rs + g * 16);
    }
}

// ======================= split / transpose kernels =======================
__global__ __launch_bounds__(256) void split_kernel(
    const float* __restrict__ x, __half* __restrict__ hi, int n4)
{
    int i = blockIdx.x * blockDim.x + threadIdx.x;
    if (i >= n4) return;
    float4 v = reinterpret_cast<const float4*>(x)[i];
    uint32_t ph[2];
    ph[0] = pack_h(__float2half(v.x), __float2half(v.y));
    ph[1] = pack_h(__float2half(v.z), __float2half(v.w));
    reinterpret_cast<uint2*>(hi)[i] = make_uint2(ph[0], ph[1]);
}

// X [B][S][D] fp32 -> Xhi AND XThi, vectorized (float4 in, uint2 out)
__global__ __launch_bounds__(256) void transplit_kernel(
    const float* __restrict__ X,
    __half* __restrict__ Xhi, __half* __restrict__ XThi)
{
    __shared__ float t[32][33];
    const int b = blockIdx.z;
    const int s0 = blockIdx.x * 32, d0 = blockIdx.y * 32;
    const int tid = threadIdx.x;
    const int ls = tid >> 3;
    const int ld = (tid & 7) * 4;
    const float* Xb = X + (size_t)b * S * D;
    __half* xh = Xhi + (size_t)b * S * D;
    {
        const size_t o = (size_t)(s0 + ls) * D + d0 + ld;
        const float4 v = *reinterpret_cast<const float4*>(Xb + o);
        t[ls][ld + 0] = v.x; t[ls][ld + 1] = v.y;
        t[ls][ld + 2] = v.z; t[ls][ld + 3] = v.w;
        uint2 ph;
        ph.x = pack_h(__float2half(v.x), __float2half(v.y));
        ph.y = pack_h(__float2half(v.z), __float2half(v.w));
        *reinterpret_cast<uint2*>(xh + o) = ph;
    }
    __syncthreads();
    const int td = tid >> 3;
    const int ts = (tid & 7) * 4;
    __half* hb = XThi + (size_t)b * D * S;
    {
        const float v0 = t[ts + 0][td];
        const float v1 = t[ts + 1][td];
        const float v2 = t[ts + 2][td];
        const float v3 = t[ts + 3][td];
        uint2 ph;
        ph.x = pack_h(__float2half(v0), __float2half(v1));
        ph.y = pack_h(__float2half(v2), __float2half(v3));
        const size_t o = (size_t)(d0 + td) * S + s0 + ts;
        *reinterpret_cast<uint2*>(hb + o) = ph;
    }
}

// ======================= fp16 1-pass MMA GEMM (128x128) =======================
// C[m][n] = alpha * sum_k A[m][k]*B[n][k]; A [MxK] rows, B [NxK] rows, K-major.
// CTA tile 128x128, BK=32, 8 warps of 64x32, 2 CTAs/SM.
// EPI=0: fp32 out. EPI=2: fp16 out.
template <int EPI>
__global__ __launch_bounds__(256, 2) void mma_gemm(
    const __half* __restrict__ Ahi_, const __half* __restrict__ Bhi_,
    float* __restrict__ outF, __half* __restrict__ outHi,
    int K, int ldC, long long sA, long long sB, long long sC, float alpha)
{
    extern __shared__ __align__(128) char smem[];
    const uint32_t sb = smem_u32(smem);
    const int tid = threadIdx.x;
    const int lane = tid & 31, wid = tid >> 5;
    const int wm = wid & 1;        // 2 m-slots of 64
    const int wn = wid >> 1;       // 4 n-slots of 32

    const size_t zb = blockIdx.z;
    const int m0 = blockIdx.y * 128, n0 = blockIdx.x * 128;
    const __half* Ahi = Ahi_ + zb * sA + (size_t)m0 * K;
    const __half* Bhi = Bhi_ + zb * sB + (size_t)n0 * K;

    float acc[4][4][4] = {};   // [mt][nt][frag]

    auto issue = [&](int stage, int kc) {
        const uint32_t s = sb + stage * STAGE;
        load_tile_t<128, 256>(s,          Ahi, K, kc, tid);
        load_tile_t<128, 256>(s + TILE_A, Bhi, K, kc, tid);
        CP_COMMIT();
    };

    const int KC = K >> 5;
    issue(0, 0);

    for (int kc = 0; kc < KC; kc++) {
        const int st = kc & 1;
        const bool more = (kc + 1) < KC;
        if (more) issue(st ^ 1, kc + 1);
        if (more) cp_wait<1>(); else cp_wait<0>();
        __syncthreads();

        const uint32_t sAhi = sb + st * STAGE;
        const uint32_t sBhi = sAhi + TILE_A;
        const int nrow = wn * 32;
        const int mrow = wm * 64;

        #pragma unroll
        for (int ks = 0; ks < 2; ks++) {
            const int kbyte = ks * 32;
            uint32_t bh[2][4];
            ldmB(sBhi, nrow,      kbyte, lane, bh[0]);
            ldmB(sBhi, nrow + 16, kbyte, lane, bh[1]);
            #pragma unroll
            for (int mt = 0; mt < 4; mt++) {
                uint32_t ah[4];
                ldmA(sAhi, mrow + mt * 16, kbyte, lane, ah);
                #pragma unroll
                for (int nt = 0; nt < 4; nt++) {
                    const uint32_t b0 = bh[nt >> 1][(nt & 1) * 2];
                    const uint32_t b1 = bh[nt >> 1][(nt & 1) * 2 + 1];
                    mma16816(acc[mt][nt], ah, b0, b1);
                }
            }
        }
        __syncthreads();
    }

    // ---- epilogue ----
    const int r0 = lane >> 2;
    const int c0 = (lane & 3) * 2;
    #pragma unroll
    for (int mt = 0; mt < 4; mt++) {
        #pragma unroll
        for (int half = 0; half < 2; half++) {
            const size_t m = (size_t)(m0 + wm * 64 + mt * 16 + r0 + half * 8);
            #pragma unroll
            for (int nt = 0; nt < 4; nt++) {
                const size_t n = (size_t)(n0 + wn * 32 + nt * 8 + c0);
                const float v0 = acc[mt][nt][half * 2 + 0] * alpha;
                const float v1 = acc[mt][nt][half * 2 + 1] * alpha;
                if (EPI == 0) {
                    float2 v = make_float2(v0, v1);
                    *reinterpret_cast<float2*>(outF + zb * sC + m * ldC + n) = v;
                } else {
                    const size_t o = zb * sC + m * ldC + n;
                    *reinterpret_cast<uint32_t*>(outHi + o) =
                        pack_h(__float2half(v0), __float2half(v1));
                }
            }
        }
    }
}

// =============== fp16 1-pass MMA GEMM, 64x64 tiles (step2) ===============
// Symmetric C = A @ A^T tiles: grid 12x12, lower triangle computed,
// off-diagonal tiles mirror-written. 128 threads, 4 warps of 32x32.
__global__ __launch_bounds__(128, 4) void mma_gemm64_sym(
    const __half* __restrict__ A_, __half* __restrict__ outHi,
    int K, int ldC, long long sA, long long sC)
{
    if (blockIdx.x > blockIdx.y) return;

    extern __shared__ __align__(128) char smem[];
    const uint32_t sb = smem_u32(smem);
    const int tid = threadIdx.x;
    const int lane = tid & 31, wid = tid >> 5;
    const int wm = wid & 1;        // 2 m-slots of 32
    const int wn = wid >> 1;       // 2 n-slots of 32

    const size_t zb = blockIdx.z;
    const int m0 = blockIdx.y * 64, n0 = blockIdx.x * 64;
    const __half* Am = A_ + zb * sA + (size_t)m0 * K;
    const __half* An = A_ + zb * sA + (size_t)n0 * K;

    float acc[2][4][4] = {};   // [mt][nt][frag]

    auto issue = [&](int stage, int kc) {
        const uint32_t s = sb + stage * STAGE64;
        load_tile_t<64, 128>(s,          Am, K, kc, tid);
        load_tile_t<64, 128>(s + TILE64, An, K, kc, tid);
        CP_COMMIT();
    };

    const int KC = K >> 5;
    issue(0, 0);

    for (int kc = 0; kc < KC; kc++) {
        const int st = kc & 1;
        const bool more = (kc + 1) < KC;
        if (more) issue(st ^ 1, kc + 1);
        if (more) cp_wait<1>(); else cp_wait<0>();
        __syncthreads();

        const uint32_t sAm = sb + st * STAGE64;
        const uint32_t sAn = sAm + TILE64;
        const int nrow = wn * 32;
        const int mrow = wm * 32;

        #pragma unroll
        for (int ks = 0; ks < 2; ks++) {
            const int kbyte = ks * 32;
            uint32_t bh[2][4];
            ldmB(sAn, nrow,      kbyte, lane, bh[0]);
            ldmB(sAn, nrow + 16, kbyte, lane, bh[1]);
            #pragma unroll
            for (int mt = 0; mt < 2; mt++) {
                uint32_t ah[4];
                ldmA(sAm, mrow + mt * 16, kbyte, lane, ah);
                #pragma unroll
                for (int nt = 0; nt < 4; nt++) {
                    const uint32_t b0 = bh[nt >> 1][(nt & 1) * 2];
                    const uint32_t b1 = bh[nt >> 1][(nt & 1) * 2 + 1];
                    mma16816(acc[mt][nt], ah, b0, b1);
                }
            }
        }
        __syncthreads();
    }

    // ---- epilogue: fp16 out + mirror for off-diagonal tiles ----
    const int r0 = lane >> 2;
    const int c0 = (lane & 3) * 2;
    const bool mir = (blockIdx.x != blockIdx.y);
    #pragma unroll
    for (int mt = 0; mt < 2; mt++) {
        #pragma unroll
        for (int half = 0; half < 2; half++) {
            const size_t m = (size_t)(m0 + wm * 32 + mt * 16 + r0 + half * 8);
            #pragma unroll
            for (int nt = 0; nt < 4; nt++) {
                const size_t n = (size_t)(n0 + wn * 32 + nt * 8 + c0);
                const __half h0 = __float2half(acc[mt][nt][half * 2 + 0]);
                const __half h1 = __float2half(acc[mt][nt][half * 2 + 1]);
                const size_t o = zb * sC + m * ldC + n;
                *reinterpret_cast<uint32_t*>(outHi + o) = pack_h(h0, h1);
                if (mir) {
                    const size_t ot = zb * sC + n * ldC + m;
                    outHi[ot] = h0;
                    outHi[ot + ldC] = h1;
                }
            }
        }
    }
}

// ============================== launcher ==============================
extern "C" void kernel_launch(void* const* d_in, const int* in_sizes, int n_in,
                              void* d_out, int out_size)
{
    const float* X  = (const float*)d_in[0];
    const float* Wq = (const float*)d_in[2];
    const float* Wk = (const float*)d_in[3];
    float* out = (float*)d_out;
    const int B = in_sizes[1];  // 8

    struct Ptrs {
        __half *Xhi, *XThi, *Qhi, *Khi, *Mhi, *Ghi, *Hhi;
    };
    static Ptrs p;
    static cudaStream_t sW = nullptr;
    static cudaEvent_t evFork = nullptr, evJoin = nullptr;
    static bool inited = false;
    if (!inited) {
        cudaGetSymbolAddress((void**)&p.Xhi, g_Xhi);
        cudaGetSymbolAddress((void**)&p.XThi, g_XThi);
        cudaGetSymbolAddress((void**)&p.Qhi, g_Qhi);
        cudaGetSymbolAddress((void**)&p.Khi, g_Khi);
        cudaGetSymbolAddress((void**)&p.Mhi, g_Mhi);
        cudaGetSymbolAddress((void**)&p.Ghi, g_Ghi);
        cudaGetSymbolAddress((void**)&p.Hhi, g_Hhi);
        cudaFuncSetAttribute((const void*)mma_gemm<2>,
                             cudaFuncAttributeMaxDynamicSharedMemorySize, SMEM_SZ);
        cudaFuncSetAttribute((const void*)mma_gemm<0>,
                             cudaFuncAttributeMaxDynamicSharedMemorySize, SMEM_SZ);
        cudaFuncSetAttribute((const void*)mma_gemm64_sym,
                             cudaFuncAttributeMaxDynamicSharedMemorySize, SMEM64);
        cudaStreamCreateWithFlags(&sW, cudaStreamNonBlocking);
        cudaEventCreateWithFlags(&evFork, cudaEventDisableTiming);
        cudaEventCreateWithFlags(&evJoin, cudaEventDisableTiming);
        inited = true;
    }

    const float alpha = 1.0f / sqrtf((float)D * (float)D * (float)D);
    const long long DD = (long long)D * D;
    const long long SD = (long long)S * D;

    // ---- fork: W path (splits + step1) on side stream ----
    cudaEventRecord(evFork, 0);
    cudaStreamWaitEvent(sW, evFork, 0);
    {
        int n4 = D * D / 4;
        split_kernel<<<(n4 + 255) / 256, 256, 0, sW>>>(Wq, p.Qhi, n4);
        split_kernel<<<(n4 + 255) / 256, 256, 0, sW>>>(Wk, p.Khi, n4);
        // 1) M = Wq @ Wk^T   [768x768], K=768 -> fp16
        mma_gemm<2><<<dim3(D / 128, D / 128, 1), 256, SMEM_SZ, sW>>>(
            p.Qhi, p.Khi, nullptr, p.Mhi, D, D, 0, 0, 0, 1.0f);
    }
    cudaEventRecord(evJoin, sW);

    // ---- main chain ----
    {
        dim3 g(S / 32, D / 32, B);
        transplit_kernel<<<g, 256>>>(X, p.Xhi, p.XThi);
    }
    // 2) G_b = XThi_b @ XThi_b^T  [768x768] x B, K=2048
    //    64x64 tiles, symmetric lower triangle (78 of 144) + mirror -> 624 CTAs
    mma_gemm64_sym<<<dim3(D / 64, D / 64, B), 128, SMEM64>>>(
        p.XThi, p.Ghi, S, D, SD, DD);

    cudaStreamWaitEvent(0, evJoin, 0);  // join W path before step3

    // 3) H^T_b = (G_b @ M^T) * alpha  [768x768] x B, K=768 -> fp16
    mma_gemm<2><<<dim3(D / 128, D / 128, B), 256, SMEM_SZ>>>(
        p.Ghi, p.Mhi, nullptr, p.Hhi, D, D, DD, 0, DD, alpha);
    // 4) Out_b = Xhi_b @ (H^T_b)^T  [2048x768] x B, K=768 -> fp32
    mma_gemm<0><<<dim3(D / 128, S / 128, B), 256, SMEM_SZ>>>(
        p.Xhi, p.Hhi, out, nullptr, D, D, SD, DD, SD, 1.0f);
}